// round 3
// baseline (speedup 1.0000x reference)
#include <cuda_runtime.h>

#define HN 100000
#define HE 1600000

// ---- scratch (static __device__ — no allocation allowed) ----
__device__ float  g_h[HN * 64];      // projected features [N,64]
__device__ float  g_el[HN * 4];      // left attention logits [N,H]
__device__ float  g_er[HN * 4];      // right attention logits [N,H]
__device__ int    g_deg[HN];         // in-degree histogram
__device__ int    g_off[HN + 1];     // CSR offsets by target
__device__ int    g_cursor[HN];      // scatter cursors
__device__ int    g_srcs[HE];        // src node per edge, sorted by target
__device__ float4 g_e4[HE];          // exp(leaky(score)) per head, sorted by target

// ---------------------------------------------------------------------------
__global__ void zero_deg_kernel(int n) {
    int i = blockIdx.x * blockDim.x + threadIdx.x;
    if (i < n) g_deg[i] = 0;
}

// ---------------------------------------------------------------------------
// Fused h = feat @ W  (+ el/er head reductions). Warp per row.
// Lane l computes output features 2l and 2l+1 (same head = l/8).
__global__ void gemm_kernel(const float* __restrict__ feat,
                            const float* __restrict__ W,
                            const float* __restrict__ attn_l,
                            const float* __restrict__ attn_r,
                            int n) {
    __shared__ float2 sW[4096];   // [k=128][lane=32] pairs (W[k][2l], W[k][2l+1])
    const float2* Wf2 = (const float2*)W;
    for (int i = threadIdx.x; i < 4096; i += blockDim.x) sW[i] = Wf2[i];
    __syncthreads();

    int lane  = threadIdx.x & 31;
    int gwarp = (blockIdx.x * blockDim.x + threadIdx.x) >> 5;
    int nwarp = (gridDim.x * blockDim.x) >> 5;

    float2 alv = ((const float2*)attn_l)[lane];
    float2 arv = ((const float2*)attn_r)[lane];
    float2* h2 = (float2*)g_h;

    for (int row = gwarp; row < n; row += nwarp) {
        const float* frow = feat + row * 128;
        float ax = 0.f, ay = 0.f;
#pragma unroll
        for (int kb = 0; kb < 128; kb += 32) {
            float fv = frow[kb + lane];
#pragma unroll
            for (int kk = 0; kk < 32; kk++) {
                float  b = __shfl_sync(0xffffffffu, fv, kk);
                float2 w = sW[(kb + kk) * 32 + lane];
                ax = fmaf(b, w.x, ax);
                ay = fmaf(b, w.y, ay);
            }
        }
        h2[row * 32 + lane] = make_float2(ax, ay);

        // head-wise reductions: sum over the 8 lanes of each head (16 feats)
        float pl = ax * alv.x + ay * alv.y;
        float pr = ax * arv.x + ay * arv.y;
#pragma unroll
        for (int m = 4; m >= 1; m >>= 1) {
            pl += __shfl_xor_sync(0xffffffffu, pl, m);
            pr += __shfl_xor_sync(0xffffffffu, pr, m);
        }
        if ((lane & 7) == 0) {
            g_el[row * 4 + (lane >> 3)] = pl;
            g_er[row * 4 + (lane >> 3)] = pr;
        }
    }
}

// ---------------------------------------------------------------------------
__global__ void hist_kernel(const int* __restrict__ trg, int e) {
    int i = blockIdx.x * blockDim.x + threadIdx.x;
    if (i < e) atomicAdd(&g_deg[trg[i]], 1);
}

// ---------------------------------------------------------------------------
// Single-block exclusive scan of g_deg -> g_off / g_cursor.
__global__ void scan_kernel(int n, int e) {
    __shared__ int part[1024];
    int t = threadIdx.x;
    int chunk = (n + 1023) >> 10;
    int lo = t * chunk;
    int hi = lo + chunk; if (hi > n) hi = n;

    int s = 0;
    for (int i = lo; i < hi; i++) s += g_deg[i];
    part[t] = s;
    __syncthreads();
    for (int d = 1; d < 1024; d <<= 1) {
        int v = (t >= d) ? part[t - d] : 0;
        __syncthreads();
        part[t] += v;
        __syncthreads();
    }
    int ex = (t == 0) ? 0 : part[t - 1];
    for (int i = lo; i < hi; i++) {
        g_off[i]    = ex;
        g_cursor[i] = ex;
        ex += g_deg[i];
    }
    if (t == 1023) g_off[n] = e;
}

// ---------------------------------------------------------------------------
// Scatter edges into CSR order + fuse e = exp(leakyrelu(el[src]+er[trg])).
// (Global max shift dropped: cancels in e/(sum_e+eps) to ~1e-14 rel; s bounded.)
__global__ void scatter_kernel(const int* __restrict__ src,
                               const int* __restrict__ trg, int e) {
    int i = blockIdx.x * blockDim.x + threadIdx.x;
    if (i >= e) return;
    int t  = trg[i];
    int sv = src[i];
    int pos = atomicAdd(&g_cursor[t], 1);
    g_srcs[pos] = sv;

    float4 elv = ((const float4*)g_el)[sv];
    float4 erv = ((const float4*)g_er)[t];
    float s0 = elv.x + erv.x, s1 = elv.y + erv.y;
    float s2 = elv.z + erv.z, s3 = elv.w + erv.w;
    s0 = s0 > 0.f ? s0 : 0.2f * s0;
    s1 = s1 > 0.f ? s1 : 0.2f * s1;
    s2 = s2 > 0.f ? s2 : 0.2f * s2;
    s3 = s3 > 0.f ? s3 : 0.2f * s3;
    g_e4[pos] = make_float4(__expf(s0), __expf(s1), __expf(s2), __expf(s3));
}

// ---------------------------------------------------------------------------
// Warp per target node: out = (sum_j e_j * h[src_j]) / (sum_j e_j + eps).
// Lane l owns features {2l, 2l+1} (head l/8) -> one LDG.64 per edge per lane.
__global__ void agg_kernel(float* __restrict__ out, int n) {
    int warp = (blockIdx.x * blockDim.x + threadIdx.x) >> 5;
    int lane = threadIdx.x & 31;
    if (warp >= n) return;

    int lo = g_off[warp];
    int hi = g_off[warp + 1];

    float accx = 0.f, accy = 0.f, den = 0.f;
    const float2* h2 = (const float2*)g_h;

    for (int j = lo; j < hi; j++) {
        int    sv = g_srcs[j];           // broadcast
        float4 ev = g_e4[j];             // broadcast
        float  w  = lane < 16 ? (lane < 8 ? ev.x : ev.y)
                              : (lane < 24 ? ev.z : ev.w);
        float2 hv = h2[sv * 32 + lane];  // coalesced 256B row
        accx = fmaf(w, hv.x, accx);
        accy = fmaf(w, hv.y, accy);
        den += w;
    }
    float inv = 1.0f / (den + 1e-16f);
    ((float2*)out)[warp * 32 + lane] = make_float2(accx * inv, accy * inv);
}

// ---------------------------------------------------------------------------
extern "C" void kernel_launch(void* const* d_in, const int* in_sizes, int n_in,
                              void* d_out, int out_size) {
    const float* feat   = (const float*)d_in[0];
    const float* W      = (const float*)d_in[1];
    const float* attn_l = (const float*)d_in[2];
    const float* attn_r = (const float*)d_in[3];
    const int*   src    = (const int*)d_in[4];
    const int*   trg    = (const int*)d_in[5];
    int n = in_sizes[0] / 128;
    int e = in_sizes[4];
    float* out = (float*)d_out;

    zero_deg_kernel<<<(n + 255) / 256, 256>>>(n);
    gemm_kernel<<<592, 256>>>(feat, W, attn_l, attn_r, n);
    hist_kernel<<<(e + 255) / 256, 256>>>(trg, e);
    scan_kernel<<<1, 1024>>>(n, e);
    scatter_kernel<<<(e + 255) / 256, 256>>>(src, trg, e);
    agg_kernel<<<(n + 7) / 8, 256>>>(out, n);
}

// round 4
// speedup vs baseline: 1.5857x; 1.5857x over previous
#include <cuda_runtime.h>

#define HN 100000
#define HE 1600000
#define SCAN_T 512
#define SCAN_B ((HN + SCAN_T - 1) / SCAN_T)   // 196

// ---- scratch (static __device__ — no allocation allowed) ----
__device__ float  g_h[HN * 64];      // projected features [N,64]
__device__ float  g_el[HN * 4];      // left attention logits [N,H]
__device__ float  g_er[HN * 4];      // right attention logits [N,H]
__device__ int    g_deg[HN];         // in-degree histogram
__device__ int    g_off[HN + 1];     // CSR offsets by target
__device__ int    g_cursor[HN];      // scatter cursors
__device__ int    g_srcs[HE];        // src node per edge, sorted by target
__device__ float4 g_e4[HE];          // exp(leaky(score)) per head, sorted by target
__device__ int    g_bsum[SCAN_B];    // per-block sums
__device__ int    g_bpre[SCAN_B];    // per-block exclusive prefixes

// ---------------------------------------------------------------------------
__global__ void zero_deg_kernel(int n) {
    int i = blockIdx.x * blockDim.x + threadIdx.x;
    if (i < n) g_deg[i] = 0;
}

// ---------------------------------------------------------------------------
// Fused h = feat @ W  (+ el/er head reductions). Warp per row.
// Lane l computes output features 2l and 2l+1 (same head = l/8).
__global__ void gemm_kernel(const float* __restrict__ feat,
                            const float* __restrict__ W,
                            const float* __restrict__ attn_l,
                            const float* __restrict__ attn_r,
                            int n) {
    __shared__ float2 sW[4096];   // [k=128][lane=32] pairs (W[k][2l], W[k][2l+1])
    const float2* Wf2 = (const float2*)W;
    for (int i = threadIdx.x; i < 4096; i += blockDim.x) sW[i] = Wf2[i];
    __syncthreads();

    int lane  = threadIdx.x & 31;
    int gwarp = (blockIdx.x * blockDim.x + threadIdx.x) >> 5;
    int nwarp = (gridDim.x * blockDim.x) >> 5;

    float2 alv = ((const float2*)attn_l)[lane];
    float2 arv = ((const float2*)attn_r)[lane];
    float2* h2 = (float2*)g_h;

    for (int row = gwarp; row < n; row += nwarp) {
        const float* frow = feat + row * 128;
        float ax = 0.f, ay = 0.f;
#pragma unroll
        for (int kb = 0; kb < 128; kb += 32) {
            float fv = frow[kb + lane];
#pragma unroll
            for (int kk = 0; kk < 32; kk++) {
                float  b = __shfl_sync(0xffffffffu, fv, kk);
                float2 w = sW[(kb + kk) * 32 + lane];
                ax = fmaf(b, w.x, ax);
                ay = fmaf(b, w.y, ay);
            }
        }
        h2[row * 32 + lane] = make_float2(ax, ay);

        // head-wise reductions: sum over the 8 lanes of each head (16 feats)
        float pl = ax * alv.x + ay * alv.y;
        float pr = ax * arv.x + ay * arv.y;
#pragma unroll
        for (int m = 4; m >= 1; m >>= 1) {
            pl += __shfl_xor_sync(0xffffffffu, pl, m);
            pr += __shfl_xor_sync(0xffffffffu, pr, m);
        }
        if ((lane & 7) == 0) {
            g_el[row * 4 + (lane >> 3)] = pl;
            g_er[row * 4 + (lane >> 3)] = pr;
        }
    }
}

// ---------------------------------------------------------------------------
__global__ void hist_kernel(const int* __restrict__ trg, int e) {
    int i = blockIdx.x * blockDim.x + threadIdx.x;
    if (i < e) atomicAdd(&g_deg[trg[i]], 1);
}

// ---------------------------------------------------------------------------
// Hierarchical scan, phase 1: per-block sums of g_deg.
__global__ void scan_bsum_kernel(int n) {
    __shared__ int ws[SCAN_T / 32];
    int i = blockIdx.x * SCAN_T + threadIdx.x;
    int v = (i < n) ? g_deg[i] : 0;
#pragma unroll
    for (int m = 16; m >= 1; m >>= 1) v += __shfl_xor_sync(0xffffffffu, v, m);
    if ((threadIdx.x & 31) == 0) ws[threadIdx.x >> 5] = v;
    __syncthreads();
    if (threadIdx.x < SCAN_T / 32) {
        int s = ws[threadIdx.x];
#pragma unroll
        for (int m = SCAN_T / 64; m >= 1; m >>= 1)
            s += __shfl_xor_sync(0xffffffffu, s, m, SCAN_T / 32);
        if (threadIdx.x == 0) g_bsum[blockIdx.x] = s;
    }
}

// Phase 2: single small block exclusive-scans the block sums (SCAN_B = 196).
__global__ void scan_bpre_kernel() {
    __shared__ int sh[256];
    int t = threadIdx.x;
    sh[t] = (t < SCAN_B) ? g_bsum[t] : 0;
    __syncthreads();
#pragma unroll
    for (int d = 1; d < 256; d <<= 1) {
        int v = (t >= d) ? sh[t - d] : 0;
        __syncthreads();
        sh[t] += v;
        __syncthreads();
    }
    if (t < SCAN_B) g_bpre[t] = (t == 0) ? 0 : sh[t - 1];
}

// Phase 3: block-local exclusive scan + block prefix -> g_off / g_cursor.
__global__ void scan_write_kernel(int n, int e) {
    __shared__ int sh[SCAN_T];
    int t = threadIdx.x;
    int i = blockIdx.x * SCAN_T + t;
    int v = (i < n) ? g_deg[i] : 0;
    sh[t] = v;
    __syncthreads();
#pragma unroll
    for (int d = 1; d < SCAN_T; d <<= 1) {
        int u = (t >= d) ? sh[t - d] : 0;
        __syncthreads();
        sh[t] += u;
        __syncthreads();
    }
    if (i < n) {
        int ex = g_bpre[blockIdx.x] + sh[t] - v;   // exclusive prefix
        g_off[i]    = ex;
        g_cursor[i] = ex;
    }
    if (i == n - 1 || (blockIdx.x == gridDim.x - 1 && t == SCAN_T - 1))
        g_off[n] = e;
}

// ---------------------------------------------------------------------------
// Scatter edges into CSR order + fuse e = exp(leakyrelu(el[src]+er[trg])).
// (Global max shift dropped: cancels in e/(sum_e+eps) to ~1e-14 rel; s bounded.)
__global__ void scatter_kernel(const int* __restrict__ src,
                               const int* __restrict__ trg, int e) {
    int i = blockIdx.x * blockDim.x + threadIdx.x;
    if (i >= e) return;
    int t  = trg[i];
    int sv = src[i];
    int pos = atomicAdd(&g_cursor[t], 1);
    g_srcs[pos] = sv;

    float4 elv = ((const float4*)g_el)[sv];
    float4 erv = ((const float4*)g_er)[t];
    float s0 = elv.x + erv.x, s1 = elv.y + erv.y;
    float s2 = elv.z + erv.z, s3 = elv.w + erv.w;
    s0 = s0 > 0.f ? s0 : 0.2f * s0;
    s1 = s1 > 0.f ? s1 : 0.2f * s1;
    s2 = s2 > 0.f ? s2 : 0.2f * s2;
    s3 = s3 > 0.f ? s3 : 0.2f * s3;
    g_e4[pos] = make_float4(__expf(s0), __expf(s1), __expf(s2), __expf(s3));
}

// ---------------------------------------------------------------------------
// Warp per target node: out = (sum_j e_j * h[src_j]) / (sum_j e_j + eps).
// Lane l owns features {2l, 2l+1} (head l/8). Unrolled x2 for MLP.
__global__ void agg_kernel(float* __restrict__ out, int n) {
    int warp = (blockIdx.x * blockDim.x + threadIdx.x) >> 5;
    int lane = threadIdx.x & 31;
    if (warp >= n) return;

    int lo = g_off[warp];
    int hi = g_off[warp + 1];

    float accx = 0.f, accy = 0.f, den = 0.f;
    const float2* h2 = (const float2*)g_h;

    int j = lo;
    for (; j + 1 < hi; j += 2) {
        int    sv0 = g_srcs[j];
        int    sv1 = g_srcs[j + 1];
        float4 ev0 = g_e4[j];
        float4 ev1 = g_e4[j + 1];
        float  w0  = lane < 16 ? (lane < 8 ? ev0.x : ev0.y)
                               : (lane < 24 ? ev0.z : ev0.w);
        float  w1  = lane < 16 ? (lane < 8 ? ev1.x : ev1.y)
                               : (lane < 24 ? ev1.z : ev1.w);
        float2 hv0 = h2[sv0 * 32 + lane];
        float2 hv1 = h2[sv1 * 32 + lane];
        accx = fmaf(w0, hv0.x, accx);
        accy = fmaf(w0, hv0.y, accy);
        accx = fmaf(w1, hv1.x, accx);
        accy = fmaf(w1, hv1.y, accy);
        den += w0 + w1;
    }
    if (j < hi) {
        int    sv = g_srcs[j];
        float4 ev = g_e4[j];
        float  w  = lane < 16 ? (lane < 8 ? ev.x : ev.y)
                              : (lane < 24 ? ev.z : ev.w);
        float2 hv = h2[sv * 32 + lane];
        accx = fmaf(w, hv.x, accx);
        accy = fmaf(w, hv.y, accy);
        den += w;
    }
    float inv = 1.0f / (den + 1e-16f);
    ((float2*)out)[warp * 32 + lane] = make_float2(accx * inv, accy * inv);
}

// ---------------------------------------------------------------------------
extern "C" void kernel_launch(void* const* d_in, const int* in_sizes, int n_in,
                              void* d_out, int out_size) {
    const float* feat   = (const float*)d_in[0];
    const float* W      = (const float*)d_in[1];
    const float* attn_l = (const float*)d_in[2];
    const float* attn_r = (const float*)d_in[3];
    const int*   src    = (const int*)d_in[4];
    const int*   trg    = (const int*)d_in[5];
    int n = in_sizes[0] / 128;
    int e = in_sizes[4];
    float* out = (float*)d_out;

    int nb = (n + SCAN_T - 1) / SCAN_T;

    zero_deg_kernel<<<(n + 255) / 256, 256>>>(n);
    gemm_kernel<<<592, 256>>>(feat, W, attn_l, attn_r, n);
    hist_kernel<<<(e + 255) / 256, 256>>>(trg, e);
    scan_bsum_kernel<<<nb, SCAN_T>>>(n);
    scan_bpre_kernel<<<1, 256>>>();
    scan_write_kernel<<<nb, SCAN_T>>>(n, e);
    scatter_kernel<<<(e + 255) / 256, 256>>>(src, trg, e);
    agg_kernel<<<(n + 7) / 8, 256>>>(out, n);
}

// round 10
// speedup vs baseline: 2.4543x; 1.5478x over previous
#include <cuda_runtime.h>

#define HN 100000
#define HE 1600000
#define SCAN_T 512
#define SCAN_B ((HN + SCAN_T - 1) / SCAN_T)   // 196

typedef unsigned long long ull;

// ---- scratch (static __device__ — no allocation allowed) ----
__device__ float  g_h[HN * 64];      // projected features [N,64]
__device__ float  g_el[HN * 4];      // left attention logits [N,H]
__device__ float  g_er[HN * 4];      // right attention logits [N,H]
__device__ int    g_deg[HN];         // in-degree histogram
__device__ int    g_off[HN + 1];     // CSR offsets by target
__device__ int    g_cursor[HN];      // scatter cursors
__device__ int    g_srcs[HE];        // src node per edge, sorted by target
__device__ float4 g_e4[HE];          // exp(leaky(score)) per head, sorted by target
__device__ int    g_bsum[SCAN_B];    // per-block sums
__device__ int    g_bpre[SCAN_B];    // per-block exclusive prefixes

// packed f32x2 FMA: d = a*b + d on both 32-bit halves
__device__ __forceinline__ void fma2(ull& d, ull a, ull b) {
    asm("fma.rn.f32x2 %0, %1, %2, %0;" : "+l"(d) : "l"(a), "l"(b));
}
__device__ __forceinline__ ull dup2(float a) {
    ull r;
    asm("mov.b64 %0, {%1, %1};" : "=l"(r) : "r"(__float_as_uint(a)));
    return r;
}

// ---------------------------------------------------------------------------
__global__ void zero_deg_kernel(int n) {
    int i = blockIdx.x * blockDim.x + threadIdx.x;
    if (i < n) g_deg[i] = 0;
}

// ---------------------------------------------------------------------------
// Tiled GEMM: h = feat @ W, fused el/er. Block = 256 rows x 64 cols,
// 256 threads, 8x8 micro-tile, packed FFMA2 accumulators (col pairs).
#define GROWS 256
#define KC 32
#define FSS  (GROWS + 4)   // 260-float stride: 16B-aligned rows (260*4 % 16 == 0)

__global__ __launch_bounds__(256, 2)
void gemm_kernel(const float* __restrict__ feat,
                 const float* __restrict__ W,
                 const float* __restrict__ attn_l,
                 const float* __restrict__ attn_r,
                 int n) {
    __shared__ float fs[KC * FSS];   // transposed feat tile: fs[k*FSS + row]
    __shared__ float wc[KC * 64];    // W chunk: wc[k*64 + c]

    int tid = threadIdx.x;
    int tc  = tid & 7;       // col group: cols tc*8 .. tc*8+7
    int tr  = tid >> 3;      // row group: rows tr*8 .. tr*8+7
    int rowbase = blockIdx.x * GROWS;

    ull acc[32];             // acc[i*4+j] = (row i, cols 2j/2j+1 of group) packed
#pragma unroll
    for (int i = 0; i < 32; i++) acc[i] = 0ull;

    for (int kc = 0; kc < 4; kc++) {
        // --- fill W chunk (coalesced float4) ---
        {
            const float4* Wf4 = (const float4*)(W + kc * KC * 64);
            float4* wdst = (float4*)wc;
#pragma unroll
            for (int i = 0; i < 2; i++) wdst[tid + i * 256] = Wf4[tid + i * 256];
        }
        // --- fill feat tile, transposed ---
#pragma unroll
        for (int j = 0; j < 8; j++) {
            int idx = tid + j * 256;          // float4 index in [256 rows][8 f4]
            int row = idx >> 3;
            int c4  = idx & 7;
            float4 v = make_float4(0.f, 0.f, 0.f, 0.f);
            if (rowbase + row < n)
                v = *(const float4*)(feat + (rowbase + row) * 128 + kc * KC + c4 * 4);
            int kb = c4 * 4;
            fs[(kb + 0) * FSS + row] = v.x;
            fs[(kb + 1) * FSS + row] = v.y;
            fs[(kb + 2) * FSS + row] = v.z;
            fs[(kb + 3) * FSS + row] = v.w;
        }
        __syncthreads();

        // --- compute ---
#pragma unroll 4
        for (int kk = 0; kk < KC; kk++) {
            const float* arow = fs + kk * FSS + tr * 8;   // 16B-aligned (FSS=260)
            float4 a03 = *(const float4*)(arow);
            float4 a47 = *(const float4*)(arow + 4);
            ull ad[8];
            ad[0] = dup2(a03.x); ad[1] = dup2(a03.y);
            ad[2] = dup2(a03.z); ad[3] = dup2(a03.w);
            ad[4] = dup2(a47.x); ad[5] = dup2(a47.y);
            ad[6] = dup2(a47.z); ad[7] = dup2(a47.w);

            const ull* brow = (const ull*)(wc + kk * 64 + tc * 8);
            ull bp0 = brow[0], bp1 = brow[1], bp2 = brow[2], bp3 = brow[3];
#pragma unroll
            for (int i = 0; i < 8; i++) {
                fma2(acc[i * 4 + 0], ad[i], bp0);
                fma2(acc[i * 4 + 1], ad[i], bp1);
                fma2(acc[i * 4 + 2], ad[i], bp2);
                fma2(acc[i * 4 + 3], ad[i], bp3);
            }
        }
        __syncthreads();
    }

    // --- epilogue: store h, fused el/er ---
    float al[8], ar[8];
#pragma unroll
    for (int j = 0; j < 8; j++) {
        al[j] = attn_l[tc * 8 + j];
        ar[j] = attn_r[tc * 8 + j];
    }
    int head = tc >> 1;

#pragma unroll
    for (int i = 0; i < 8; i++) {
        int r = rowbase + tr * 8 + i;
        float h[8];
#pragma unroll
        for (int j = 0; j < 4; j++) {
            float2 p = *(float2*)&acc[i * 4 + j];
            h[2 * j] = p.x; h[2 * j + 1] = p.y;
        }
        if (r < n) {
            float4* dst = (float4*)(g_h + r * 64 + tc * 8);
            dst[0] = make_float4(h[0], h[1], h[2], h[3]);
            dst[1] = make_float4(h[4], h[5], h[6], h[7]);
        }
        float pl = 0.f, pr = 0.f;
#pragma unroll
        for (int j = 0; j < 8; j++) {
            pl = fmaf(h[j], al[j], pl);
            pr = fmaf(h[j], ar[j], pr);
        }
        pl += __shfl_xor_sync(0xffffffffu, pl, 1);
        pr += __shfl_xor_sync(0xffffffffu, pr, 1);
        if (!(tc & 1) && r < n) {
            g_el[r * 4 + head] = pl;
            g_er[r * 4 + head] = pr;
        }
    }
}

// ---------------------------------------------------------------------------
__global__ void hist_kernel(const int* __restrict__ trg, int e) {
    int i = blockIdx.x * blockDim.x + threadIdx.x;
    if (i < e) atomicAdd(&g_deg[trg[i]], 1);
}

// ---------------------------------------------------------------------------
__global__ void scan_bsum_kernel(int n) {
    __shared__ int ws[SCAN_T / 32];
    int i = blockIdx.x * SCAN_T + threadIdx.x;
    int v = (i < n) ? g_deg[i] : 0;
#pragma unroll
    for (int m = 16; m >= 1; m >>= 1) v += __shfl_xor_sync(0xffffffffu, v, m);
    if ((threadIdx.x & 31) == 0) ws[threadIdx.x >> 5] = v;
    __syncthreads();
    if (threadIdx.x < SCAN_T / 32) {
        int s = ws[threadIdx.x];
#pragma unroll
        for (int m = SCAN_T / 64; m >= 1; m >>= 1)
            s += __shfl_xor_sync(0xffffffffu, s, m, SCAN_T / 32);
        if (threadIdx.x == 0) g_bsum[blockIdx.x] = s;
    }
}

__global__ void scan_bpre_kernel() {
    __shared__ int sh[256];
    int t = threadIdx.x;
    sh[t] = (t < SCAN_B) ? g_bsum[t] : 0;
    __syncthreads();
#pragma unroll
    for (int d = 1; d < 256; d <<= 1) {
        int v = (t >= d) ? sh[t - d] : 0;
        __syncthreads();
        sh[t] += v;
        __syncthreads();
    }
    if (t < SCAN_B) g_bpre[t] = (t == 0) ? 0 : sh[t - 1];
}

__global__ void scan_write_kernel(int n, int e) {
    __shared__ int sh[SCAN_T];
    int t = threadIdx.x;
    int i = blockIdx.x * SCAN_T + t;
    int v = (i < n) ? g_deg[i] : 0;
    sh[t] = v;
    __syncthreads();
#pragma unroll
    for (int d = 1; d < SCAN_T; d <<= 1) {
        int u = (t >= d) ? sh[t - d] : 0;
        __syncthreads();
        sh[t] += u;
        __syncthreads();
    }
    if (i < n) {
        int ex = g_bpre[blockIdx.x] + sh[t] - v;
        g_off[i]    = ex;
        g_cursor[i] = ex;
    }
    if (blockIdx.x == gridDim.x - 1 && t == SCAN_T - 1) g_off[n] = e;
}

// ---------------------------------------------------------------------------
__global__ void scatter_kernel(const int* __restrict__ src,
                               const int* __restrict__ trg, int e) {
    int i = blockIdx.x * blockDim.x + threadIdx.x;
    if (i >= e) return;
    int t  = trg[i];
    int sv = src[i];
    int pos = atomicAdd(&g_cursor[t], 1);
    g_srcs[pos] = sv;

    float4 elv = ((const float4*)g_el)[sv];
    float4 erv = ((const float4*)g_er)[t];
    float s0 = elv.x + erv.x, s1 = elv.y + erv.y;
    float s2 = elv.z + erv.z, s3 = elv.w + erv.w;
    s0 = s0 > 0.f ? s0 : 0.2f * s0;
    s1 = s1 > 0.f ? s1 : 0.2f * s1;
    s2 = s2 > 0.f ? s2 : 0.2f * s2;
    s3 = s3 > 0.f ? s3 : 0.2f * s3;
    g_e4[pos] = make_float4(__expf(s0), __expf(s1), __expf(s2), __expf(s3));
}

// ---------------------------------------------------------------------------
__global__ void agg_kernel(float* __restrict__ out, int n) {
    int warp = (blockIdx.x * blockDim.x + threadIdx.x) >> 5;
    int lane = threadIdx.x & 31;
    if (warp >= n) return;

    int lo = g_off[warp];
    int hi = g_off[warp + 1];

    float accx = 0.f, accy = 0.f, den = 0.f;
    const float2* h2 = (const float2*)g_h;

    int j = lo;
    for (; j + 1 < hi; j += 2) {
        int    sv0 = g_srcs[j];
        int    sv1 = g_srcs[j + 1];
        float4 ev0 = g_e4[j];
        float4 ev1 = g_e4[j + 1];
        float  w0  = lane < 16 ? (lane < 8 ? ev0.x : ev0.y)
                               : (lane < 24 ? ev0.z : ev0.w);
        float  w1  = lane < 16 ? (lane < 8 ? ev1.x : ev1.y)
                               : (lane < 24 ? ev1.z : ev1.w);
        float2 hv0 = h2[sv0 * 32 + lane];
        float2 hv1 = h2[sv1 * 32 + lane];
        accx = fmaf(w0, hv0.x, accx);
        accy = fmaf(w0, hv0.y, accy);
        accx = fmaf(w1, hv1.x, accx);
        accy = fmaf(w1, hv1.y, accy);
        den += w0 + w1;
    }
    if (j < hi) {
        int    sv = g_srcs[j];
        float4 ev = g_e4[j];
        float  w  = lane < 16 ? (lane < 8 ? ev.x : ev.y)
                              : (lane < 24 ? ev.z : ev.w);
        float2 hv = h2[sv * 32 + lane];
        accx = fmaf(w, hv.x, accx);
        accy = fmaf(w, hv.y, accy);
        den += w;
    }
    float inv = 1.0f / (den + 1e-16f);
    ((float2*)out)[warp * 32 + lane] = make_float2(accx * inv, accy * inv);
}

// ---------------------------------------------------------------------------
extern "C" void kernel_launch(void* const* d_in, const int* in_sizes, int n_in,
                              void* d_out, int out_size) {
    const float* feat   = (const float*)d_in[0];
    const float* W      = (const float*)d_in[1];
    const float* attn_l = (const float*)d_in[2];
    const float* attn_r = (const float*)d_in[3];
    const int*   src    = (const int*)d_in[4];
    const int*   trg    = (const int*)d_in[5];
    int n = in_sizes[0] / 128;
    int e = in_sizes[4];
    float* out = (float*)d_out;

    int nb = (n + SCAN_T - 1) / SCAN_T;
    int gb = (n + GROWS - 1) / GROWS;

    zero_deg_kernel<<<(n + 255) / 256, 256>>>(n);
    gemm_kernel<<<gb, 256>>>(feat, W, attn_l, attn_r, n);
    hist_kernel<<<(e + 255) / 256, 256>>>(trg, e);
    scan_bsum_kernel<<<nb, SCAN_T>>>(n);
    scan_bpre_kernel<<<1, 256>>>();
    scan_write_kernel<<<nb, SCAN_T>>>(n, e);
    scatter_kernel<<<(e + 255) / 256, 256>>>(src, trg, e);
    agg_kernel<<<(n + 7) / 8, 256>>>(out, n);
}

// round 11
// speedup vs baseline: 2.7080x; 1.1034x over previous
#include <cuda_runtime.h>
#include <cuda_fp16.h>

#define HN 100000
#define HE 1600000
#define SCAN_T 512
#define SCAN_B ((HN + SCAN_T - 1) / SCAN_T)   // 196

typedef unsigned long long ull;

// ---- scratch (static __device__ — no allocation allowed) ----
__device__ __half2 g_h2[HN * 32];    // projected features fp16 [N,64] as 32 half2/row
__device__ float  g_el[HN * 4];      // left attention logits [N,H] (fp32)
__device__ float  g_er[HN * 4];      // right attention logits [N,H] (fp32)
__device__ int    g_deg[HN];         // in-degree histogram (zero on entry; reset by scan_write)
__device__ int    g_off[HN + 1];     // CSR offsets by target
__device__ int    g_cursor[HN];      // scatter cursors
__device__ int    g_srcs[HE];        // src node per edge, sorted by target
__device__ float4 g_e4[HE];          // exp(leaky(score)) per head, sorted by target
__device__ int    g_bsum[SCAN_B];    // per-block sums

// packed f32x2 FMA: d = a*b + d on both 32-bit halves
__device__ __forceinline__ void fma2(ull& d, ull a, ull b) {
    asm("fma.rn.f32x2 %0, %1, %2, %0;" : "+l"(d) : "l"(a), "l"(b));
}
__device__ __forceinline__ ull dup2(float a) {
    ull r;
    asm("mov.b64 %0, {%1, %1};" : "=l"(r) : "r"(__float_as_uint(a)));
    return r;
}

// ---------------------------------------------------------------------------
// Tiled GEMM: h = feat @ W, fused el/er + fused in-degree histogram.
// Block = 256 rows x 64 cols, 256 threads, 8x8 micro-tile, FFMA2 accumulators.
#define GROWS 256
#define KC 32
#define FSS  (GROWS + 4)   // 260-float stride: 16B-aligned rows

__global__ __launch_bounds__(256, 2)
void gemm_kernel(const float* __restrict__ feat,
                 const float* __restrict__ W,
                 const float* __restrict__ attn_l,
                 const float* __restrict__ attn_r,
                 const int* __restrict__ trg,
                 int n, int e) {
    __shared__ float fs[KC * FSS];   // transposed feat tile: fs[k*FSS + row]
    __shared__ float wc[KC * 64];    // W chunk: wc[k*64 + c]

    int tid = threadIdx.x;

    // --- fused histogram: REDG fire-and-forget, hidden under FMA work ---
    {
        int stride = gridDim.x * 256;
#pragma unroll 4
        for (int i = blockIdx.x * 256 + tid; i < e; i += stride)
            atomicAdd(&g_deg[trg[i]], 1);
    }

    int tc  = tid & 7;       // col group: cols tc*8 .. tc*8+7
    int tr  = tid >> 3;      // row group: rows tr*8 .. tr*8+7
    int rowbase = blockIdx.x * GROWS;

    ull acc[32];             // acc[i*4+j] = (row i, cols 2j/2j+1 of group) packed
#pragma unroll
    for (int i = 0; i < 32; i++) acc[i] = 0ull;

    for (int kc = 0; kc < 4; kc++) {
        // --- fill W chunk (coalesced float4) ---
        {
            const float4* Wf4 = (const float4*)(W + kc * KC * 64);
            float4* wdst = (float4*)wc;
#pragma unroll
            for (int i = 0; i < 2; i++) wdst[tid + i * 256] = Wf4[tid + i * 256];
        }
        // --- fill feat tile, transposed ---
#pragma unroll
        for (int j = 0; j < 8; j++) {
            int idx = tid + j * 256;          // float4 index in [256 rows][8 f4]
            int row = idx >> 3;
            int c4  = idx & 7;
            float4 v = make_float4(0.f, 0.f, 0.f, 0.f);
            if (rowbase + row < n)
                v = *(const float4*)(feat + (rowbase + row) * 128 + kc * KC + c4 * 4);
            int kb = c4 * 4;
            fs[(kb + 0) * FSS + row] = v.x;
            fs[(kb + 1) * FSS + row] = v.y;
            fs[(kb + 2) * FSS + row] = v.z;
            fs[(kb + 3) * FSS + row] = v.w;
        }
        __syncthreads();

        // --- compute ---
#pragma unroll 4
        for (int kk = 0; kk < KC; kk++) {
            const float* arow = fs + kk * FSS + tr * 8;   // 16B-aligned
            float4 a03 = *(const float4*)(arow);
            float4 a47 = *(const float4*)(arow + 4);
            ull ad[8];
            ad[0] = dup2(a03.x); ad[1] = dup2(a03.y);
            ad[2] = dup2(a03.z); ad[3] = dup2(a03.w);
            ad[4] = dup2(a47.x); ad[5] = dup2(a47.y);
            ad[6] = dup2(a47.z); ad[7] = dup2(a47.w);

            const ull* brow = (const ull*)(wc + kk * 64 + tc * 8);
            ull bp0 = brow[0], bp1 = brow[1], bp2 = brow[2], bp3 = brow[3];
#pragma unroll
            for (int i = 0; i < 8; i++) {
                fma2(acc[i * 4 + 0], ad[i], bp0);
                fma2(acc[i * 4 + 1], ad[i], bp1);
                fma2(acc[i * 4 + 2], ad[i], bp2);
                fma2(acc[i * 4 + 3], ad[i], bp3);
            }
        }
        __syncthreads();
    }

    // --- epilogue: store h (fp16), fused el/er (fp32) ---
    float al[8], ar[8];
#pragma unroll
    for (int j = 0; j < 8; j++) {
        al[j] = attn_l[tc * 8 + j];
        ar[j] = attn_r[tc * 8 + j];
    }
    int head = tc >> 1;

#pragma unroll
    for (int i = 0; i < 8; i++) {
        int r = rowbase + tr * 8 + i;
        float h[8];
#pragma unroll
        for (int j = 0; j < 4; j++) {
            float2 p = *(float2*)&acc[i * 4 + j];
            h[2 * j] = p.x; h[2 * j + 1] = p.y;
        }
        if (r < n) {
            __half2 p0 = __floats2half2_rn(h[0], h[1]);
            __half2 p1 = __floats2half2_rn(h[2], h[3]);
            __half2 p2 = __floats2half2_rn(h[4], h[5]);
            __half2 p3 = __floats2half2_rn(h[6], h[7]);
            uint2* dst = (uint2*)&g_h2[r * 32 + tc * 4];
            dst[0] = make_uint2(*(unsigned*)&p0, *(unsigned*)&p1);
            dst[1] = make_uint2(*(unsigned*)&p2, *(unsigned*)&p3);
        }
        float pl = 0.f, pr = 0.f;
#pragma unroll
        for (int j = 0; j < 8; j++) {
            pl = fmaf(h[j], al[j], pl);
            pr = fmaf(h[j], ar[j], pr);
        }
        pl += __shfl_xor_sync(0xffffffffu, pl, 1);
        pr += __shfl_xor_sync(0xffffffffu, pr, 1);
        if (!(tc & 1) && r < n) {
            g_el[r * 4 + head] = pl;
            g_er[r * 4 + head] = pr;
        }
    }
}

// ---------------------------------------------------------------------------
__global__ void scan_bsum_kernel(int n) {
    __shared__ int ws[SCAN_T / 32];
    int i = blockIdx.x * SCAN_T + threadIdx.x;
    int v = (i < n) ? g_deg[i] : 0;
#pragma unroll
    for (int m = 16; m >= 1; m >>= 1) v += __shfl_xor_sync(0xffffffffu, v, m);
    if ((threadIdx.x & 31) == 0) ws[threadIdx.x >> 5] = v;
    __syncthreads();
    if (threadIdx.x < SCAN_T / 32) {
        int s = ws[threadIdx.x];
#pragma unroll
        for (int m = SCAN_T / 64; m >= 1; m >>= 1)
            s += __shfl_xor_sync(0xffffffffu, s, m, SCAN_T / 32);
        if (threadIdx.x == 0) g_bsum[blockIdx.x] = s;
    }
}

// Fused: per-block prefix over g_bsum + block-local exclusive scan ->
// g_off/g_cursor, and resets g_deg to 0 for the next invocation.
__global__ void scan_write_kernel(int n, int e) {
    __shared__ int sh[SCAN_T];
    __shared__ int bprefix;
    int t = threadIdx.x;

    // block prefix: sum of g_bsum[k] for k < blockIdx.x
    {
        int bv = (t < SCAN_B && t < (int)blockIdx.x) ? g_bsum[t] : 0;
#pragma unroll
        for (int m = 16; m >= 1; m >>= 1) bv += __shfl_xor_sync(0xffffffffu, bv, m);
        if ((t & 31) == 0) sh[t >> 5] = bv;
        __syncthreads();
        if (t == 0) {
            int s = 0;
#pragma unroll
            for (int w = 0; w < SCAN_T / 32; w++) s += sh[w];
            bprefix = s;
        }
        __syncthreads();
    }

    int i = blockIdx.x * SCAN_T + t;
    int v = (i < n) ? g_deg[i] : 0;
    sh[t] = v;
    __syncthreads();
#pragma unroll
    for (int d = 1; d < SCAN_T; d <<= 1) {
        int u = (t >= d) ? sh[t - d] : 0;
        __syncthreads();
        sh[t] += u;
        __syncthreads();
    }
    if (i < n) {
        int ex = bprefix + sh[t] - v;
        g_off[i]    = ex;
        g_cursor[i] = ex;
        g_deg[i]    = 0;           // reset for next kernel_launch call
    }
    if (blockIdx.x == gridDim.x - 1 && t == SCAN_T - 1) g_off[n] = e;
}

// ---------------------------------------------------------------------------
__global__ void scatter_kernel(const int* __restrict__ src,
                               const int* __restrict__ trg, int e) {
    int i = blockIdx.x * blockDim.x + threadIdx.x;
    if (i >= e) return;
    int t  = trg[i];
    int sv = src[i];
    int pos = atomicAdd(&g_cursor[t], 1);
    g_srcs[pos] = sv;

    float4 elv = ((const float4*)g_el)[sv];
    float4 erv = ((const float4*)g_er)[t];
    float s0 = elv.x + erv.x, s1 = elv.y + erv.y;
    float s2 = elv.z + erv.z, s3 = elv.w + erv.w;
    s0 = s0 > 0.f ? s0 : 0.2f * s0;
    s1 = s1 > 0.f ? s1 : 0.2f * s1;
    s2 = s2 > 0.f ? s2 : 0.2f * s2;
    s3 = s3 > 0.f ? s3 : 0.2f * s3;
    g_e4[pos] = make_float4(__expf(s0), __expf(s1), __expf(s2), __expf(s3));
}

// ---------------------------------------------------------------------------
// Warp per target node. Lane l owns features {2l,2l+1} (one half2), head l/8.
__global__ void agg_kernel(float* __restrict__ out, int n) {
    int warp = (blockIdx.x * blockDim.x + threadIdx.x) >> 5;
    int lane = threadIdx.x & 31;
    if (warp >= n) return;

    int lo = g_off[warp];
    int hi = g_off[warp + 1];

    float accx = 0.f, accy = 0.f, den = 0.f;

    int j = lo;
    for (; j + 1 < hi; j += 2) {
        int    sv0 = g_srcs[j];
        int    sv1 = g_srcs[j + 1];
        float4 ev0 = g_e4[j];
        float4 ev1 = g_e4[j + 1];
        float  w0  = lane < 16 ? (lane < 8 ? ev0.x : ev0.y)
                               : (lane < 24 ? ev0.z : ev0.w);
        float  w1  = lane < 16 ? (lane < 8 ? ev1.x : ev1.y)
                               : (lane < 24 ? ev1.z : ev1.w);
        float2 hv0 = __half22float2(g_h2[sv0 * 32 + lane]);
        float2 hv1 = __half22float2(g_h2[sv1 * 32 + lane]);
        accx = fmaf(w0, hv0.x, accx);
        accy = fmaf(w0, hv0.y, accy);
        accx = fmaf(w1, hv1.x, accx);
        accy = fmaf(w1, hv1.y, accy);
        den += w0 + w1;
    }
    if (j < hi) {
        int    sv = g_srcs[j];
        float4 ev = g_e4[j];
        float  w  = lane < 16 ? (lane < 8 ? ev.x : ev.y)
                              : (lane < 24 ? ev.z : ev.w);
        float2 hv = __half22float2(g_h2[sv * 32 + lane]);
        accx = fmaf(w, hv.x, accx);
        accy = fmaf(w, hv.y, accy);
        den += w;
    }
    float inv = 1.0f / (den + 1e-16f);
    ((float2*)out)[warp * 32 + lane] = make_float2(accx * inv, accy * inv);
}

// ---------------------------------------------------------------------------
extern "C" void kernel_launch(void* const* d_in, const int* in_sizes, int n_in,
                              void* d_out, int out_size) {
    const float* feat   = (const float*)d_in[0];
    const float* W      = (const float*)d_in[1];
    const float* attn_l = (const float*)d_in[2];
    const float* attn_r = (const float*)d_in[3];
    const int*   src    = (const int*)d_in[4];
    const int*   trg    = (const int*)d_in[5];
    int n = in_sizes[0] / 128;
    int e = in_sizes[4];
    float* out = (float*)d_out;

    int nb = (n + SCAN_T - 1) / SCAN_T;
    int gb = (n + GROWS - 1) / GROWS;

    gemm_kernel<<<gb, 256>>>(feat, W, attn_l, attn_r, trg, n, e);   // + fused hist
    scan_bsum_kernel<<<nb, SCAN_T>>>(n);
    scan_write_kernel<<<nb, SCAN_T>>>(n, e);                        // + fused bpre + deg reset
    scatter_kernel<<<(e + 255) / 256, 256>>>(src, trg, e);
    agg_kernel<<<(n + 7) / 8, 256>>>(out, n);
}

// round 14
// speedup vs baseline: 3.0520x; 1.1270x over previous
#include <cuda_runtime.h>
#include <cuda_fp16.h>

#define HN 100000
#define HE 1600000
#define SCAN_T 512
#define SCAN_B ((HN + SCAN_T - 1) / SCAN_T)   // 196

typedef unsigned long long ull;

// ---- scratch (static __device__ — no allocation allowed) ----
__device__ __half2 g_h2[HN * 32];    // projected features fp16 [N,64] as 32 half2/row
__device__ float  g_el[HN * 4];      // left attention logits [N,H] (fp32)
__device__ float  g_er[HN * 4];      // right attention logits [N,H] (fp32)
__device__ int    g_deg[HN];         // in-degree histogram (zero on entry; reset by scan_write)
__device__ int    g_off[HN + 1];     // CSR offsets by target
__device__ int    g_cursor[HN];      // scatter cursors
__device__ int    g_srcs[HE];        // src node per edge, grouped by target
__device__ int    g_bsum[SCAN_B];    // per-block sums

// packed f32x2 FMA: d = a*b + d on both 32-bit halves
__device__ __forceinline__ void fma2(ull& d, ull a, ull b) {
    asm("fma.rn.f32x2 %0, %1, %2, %0;" : "+l"(d) : "l"(a), "l"(b));
}
__device__ __forceinline__ ull dup2(float a) {
    ull r;
    asm("mov.b64 %0, {%1, %1};" : "=l"(r) : "r"(__float_as_uint(a)));
    return r;
}

// ---------------------------------------------------------------------------
// Tiled GEMM: h = feat @ W, fused el/er + fused in-degree histogram.
#define GROWS 256
#define KC 32
#define FSS  (GROWS + 4)   // 260-float stride: 16B-aligned rows

__global__ __launch_bounds__(256, 2)
void gemm_kernel(const float* __restrict__ feat,
                 const float* __restrict__ W,
                 const float* __restrict__ attn_l,
                 const float* __restrict__ attn_r,
                 const int* __restrict__ trg,
                 int n, int e) {
    __shared__ float fs[KC * FSS];   // transposed feat tile: fs[k*FSS + row]
    __shared__ float wc[KC * 64];    // W chunk: wc[k*64 + c]

    int tid = threadIdx.x;

    // --- fused histogram: REDG fire-and-forget, hidden under FMA work ---
    {
        int stride = gridDim.x * 256;
#pragma unroll 4
        for (int i = blockIdx.x * 256 + tid; i < e; i += stride)
            atomicAdd(&g_deg[trg[i]], 1);
    }

    int tc  = tid & 7;       // col group: cols tc*8 .. tc*8+7
    int tr  = tid >> 3;      // row group: rows tr*8 .. tr*8+7
    int rowbase = blockIdx.x * GROWS;

    ull acc[32];
#pragma unroll
    for (int i = 0; i < 32; i++) acc[i] = 0ull;

    for (int kc = 0; kc < 4; kc++) {
        {
            const float4* Wf4 = (const float4*)(W + kc * KC * 64);
            float4* wdst = (float4*)wc;
#pragma unroll
            for (int i = 0; i < 2; i++) wdst[tid + i * 256] = Wf4[tid + i * 256];
        }
#pragma unroll
        for (int j = 0; j < 8; j++) {
            int idx = tid + j * 256;
            int row = idx >> 3;
            int c4  = idx & 7;
            float4 v = make_float4(0.f, 0.f, 0.f, 0.f);
            if (rowbase + row < n)
                v = *(const float4*)(feat + (rowbase + row) * 128 + kc * KC + c4 * 4);
            int kb = c4 * 4;
            fs[(kb + 0) * FSS + row] = v.x;
            fs[(kb + 1) * FSS + row] = v.y;
            fs[(kb + 2) * FSS + row] = v.z;
            fs[(kb + 3) * FSS + row] = v.w;
        }
        __syncthreads();

#pragma unroll 4
        for (int kk = 0; kk < KC; kk++) {
            const float* arow = fs + kk * FSS + tr * 8;
            float4 a03 = *(const float4*)(arow);
            float4 a47 = *(const float4*)(arow + 4);
            ull ad[8];
            ad[0] = dup2(a03.x); ad[1] = dup2(a03.y);
            ad[2] = dup2(a03.z); ad[3] = dup2(a03.w);
            ad[4] = dup2(a47.x); ad[5] = dup2(a47.y);
            ad[6] = dup2(a47.z); ad[7] = dup2(a47.w);

            const ull* brow = (const ull*)(wc + kk * 64 + tc * 8);
            ull bp0 = brow[0], bp1 = brow[1], bp2 = brow[2], bp3 = brow[3];
#pragma unroll
            for (int i = 0; i < 8; i++) {
                fma2(acc[i * 4 + 0], ad[i], bp0);
                fma2(acc[i * 4 + 1], ad[i], bp1);
                fma2(acc[i * 4 + 2], ad[i], bp2);
                fma2(acc[i * 4 + 3], ad[i], bp3);
            }
        }
        __syncthreads();
    }

    // --- epilogue: store h (fp16), fused el/er (fp32) ---
    float al[8], ar[8];
#pragma unroll
    for (int j = 0; j < 8; j++) {
        al[j] = attn_l[tc * 8 + j];
        ar[j] = attn_r[tc * 8 + j];
    }
    int head = tc >> 1;

#pragma unroll
    for (int i = 0; i < 8; i++) {
        int r = rowbase + tr * 8 + i;
        float h[8];
#pragma unroll
        for (int j = 0; j < 4; j++) {
            float2 p = *(float2*)&acc[i * 4 + j];
            h[2 * j] = p.x; h[2 * j + 1] = p.y;
        }
        if (r < n) {
            __half2 p0 = __floats2half2_rn(h[0], h[1]);
            __half2 p1 = __floats2half2_rn(h[2], h[3]);
            __half2 p2 = __floats2half2_rn(h[4], h[5]);
            __half2 p3 = __floats2half2_rn(h[6], h[7]);
            uint2* dst = (uint2*)&g_h2[r * 32 + tc * 4];
            dst[0] = make_uint2(*(unsigned*)&p0, *(unsigned*)&p1);
            dst[1] = make_uint2(*(unsigned*)&p2, *(unsigned*)&p3);
        }
        float pl = 0.f, pr = 0.f;
#pragma unroll
        for (int j = 0; j < 8; j++) {
            pl = fmaf(h[j], al[j], pl);
            pr = fmaf(h[j], ar[j], pr);
        }
        pl += __shfl_xor_sync(0xffffffffu, pl, 1);
        pr += __shfl_xor_sync(0xffffffffu, pr, 1);
        if (!(tc & 1) && r < n) {
            g_el[r * 4 + head] = pl;
            g_er[r * 4 + head] = pr;
        }
    }
}

// ---------------------------------------------------------------------------
__global__ void scan_bsum_kernel(int n) {
    __shared__ int ws[SCAN_T / 32];
    int i = blockIdx.x * SCAN_T + threadIdx.x;
    int v = (i < n) ? g_deg[i] : 0;
#pragma unroll
    for (int m = 16; m >= 1; m >>= 1) v += __shfl_xor_sync(0xffffffffu, v, m);
    if ((threadIdx.x & 31) == 0) ws[threadIdx.x >> 5] = v;
    __syncthreads();
    if (threadIdx.x < SCAN_T / 32) {
        int s = ws[threadIdx.x];
#pragma unroll
        for (int m = SCAN_T / 64; m >= 1; m >>= 1)
            s += __shfl_xor_sync(0xffffffffu, s, m, SCAN_T / 32);
        if (threadIdx.x == 0) g_bsum[blockIdx.x] = s;
    }
}

// Fused: block prefix over g_bsum + block-local exclusive scan -> g_off/g_cursor,
// and resets g_deg for the next invocation.
__global__ void scan_write_kernel(int n, int e) {
    __shared__ int sh[SCAN_T];
    __shared__ int bprefix;
    int t = threadIdx.x;

    {
        int bv = (t < SCAN_B && t < (int)blockIdx.x) ? g_bsum[t] : 0;
#pragma unroll
        for (int m = 16; m >= 1; m >>= 1) bv += __shfl_xor_sync(0xffffffffu, bv, m);
        if ((t & 31) == 0) sh[t >> 5] = bv;
        __syncthreads();
        if (t == 0) {
            int s = 0;
#pragma unroll
            for (int w = 0; w < SCAN_T / 32; w++) s += sh[w];
            bprefix = s;
        }
        __syncthreads();
    }

    int i = blockIdx.x * SCAN_T + t;
    int v = (i < n) ? g_deg[i] : 0;
    sh[t] = v;
    __syncthreads();
#pragma unroll
    for (int d = 1; d < SCAN_T; d <<= 1) {
        int u = (t >= d) ? sh[t - d] : 0;
        __syncthreads();
        sh[t] += u;
        __syncthreads();
    }
    if (i < n) {
        int ex = bprefix + sh[t] - v;
        g_off[i]    = ex;
        g_cursor[i] = ex;
        g_deg[i]    = 0;
    }
    if (blockIdx.x == gridDim.x - 1 && t == SCAN_T - 1) g_off[n] = e;
}

// ---------------------------------------------------------------------------
// Slim scatter: CSR ordering only (no attention math). 2 edges/thread for MLP.
__global__ void scatter_kernel(const int* __restrict__ src,
                               const int* __restrict__ trg, int e) {
    int i = (blockIdx.x * blockDim.x + threadIdx.x) * 2;
    if (i + 1 < e) {
        int2 t2 = *(const int2*)(trg + i);
        int2 s2 = *(const int2*)(src + i);
        int p0 = atomicAdd(&g_cursor[t2.x], 1);
        int p1 = atomicAdd(&g_cursor[t2.y], 1);
        g_srcs[p0] = s2.x;
        g_srcs[p1] = s2.y;
    } else if (i < e) {
        int p = atomicAdd(&g_cursor[trg[i]], 1);
        g_srcs[p] = src[i];
    }
}

// ---------------------------------------------------------------------------
// Warp per target node. Lane l owns features {2l,2l+1} (one half2), head l>>3.
// Attention weight computed in-flight: w = exp(leaky(el[sv][h] + er[t][h])).
// (exp is one warp-wide MUFU instruction per edge — hidden under memory latency.)
__global__ void agg_kernel(float* __restrict__ out, int n) {
    int warp = (blockIdx.x * blockDim.x + threadIdx.x) >> 5;
    int lane = threadIdx.x & 31;
    if (warp >= n) return;

    int lo = g_off[warp];
    int hi = g_off[warp + 1];
    int head = lane >> 3;
    float er_h = g_er[warp * 4 + head];   // per-warp constant

    float accx = 0.f, accy = 0.f, den = 0.f;

    int j = lo;
    for (; j + 1 < hi; j += 2) {
        int sv0 = g_srcs[j];
        int sv1 = g_srcs[j + 1];
        float  el0 = g_el[sv0 * 4 + head];          // broadcast sector
        float  el1 = g_el[sv1 * 4 + head];
        float2 hv0 = __half22float2(g_h2[sv0 * 32 + lane]);
        float2 hv1 = __half22float2(g_h2[sv1 * 32 + lane]);
        float s0 = el0 + er_h;  s0 = s0 > 0.f ? s0 : 0.2f * s0;
        float s1 = el1 + er_h;  s1 = s1 > 0.f ? s1 : 0.2f * s1;
        float w0 = __expf(s0);
        float w1 = __expf(s1);
        accx = fmaf(w0, hv0.x, accx);
        accy = fmaf(w0, hv0.y, accy);
        accx = fmaf(w1, hv1.x, accx);
        accy = fmaf(w1, hv1.y, accy);
        den += w0 + w1;
    }
    if (j < hi) {
        int sv = g_srcs[j];
        float  el = g_el[sv * 4 + head];
        float2 hv = __half22float2(g_h2[sv * 32 + lane]);
        float s = el + er_h;  s = s > 0.f ? s : 0.2f * s;
        float w = __expf(s);
        accx = fmaf(w, hv.x, accx);
        accy = fmaf(w, hv.y, accy);
        den += w;
    }
    float inv = 1.0f / (den + 1e-16f);
    ((float2*)out)[warp * 32 + lane] = make_float2(accx * inv, accy * inv);
}

// ---------------------------------------------------------------------------
extern "C" void kernel_launch(void* const* d_in, const int* in_sizes, int n_in,
                              void* d_out, int out_size) {
    const float* feat   = (const float*)d_in[0];
    const float* W      = (const float*)d_in[1];
    const float* attn_l = (const float*)d_in[2];
    const float* attn_r = (const float*)d_in[3];
    const int*   src    = (const int*)d_in[4];
    const int*   trg    = (const int*)d_in[5];
    int n = in_sizes[0] / 128;
    int e = in_sizes[4];
    float* out = (float*)d_out;

    int nb = (n + SCAN_T - 1) / SCAN_T;
    int gb = (n + GROWS - 1) / GROWS;

    gemm_kernel<<<gb, 256>>>(feat, W, attn_l, attn_r, trg, n, e);   // + fused hist
    scan_bsum_kernel<<<nb, SCAN_T>>>(n);
    scan_write_kernel<<<nb, SCAN_T>>>(n, e);                        // + fused bpre + deg reset
    scatter_kernel<<<(e / 2 + 255) / 256, 256>>>(src, trg, e);
    agg_kernel<<<(n + 7) / 8, 256>>>(out, n);
}